// round 11
// baseline (speedup 1.0000x reference)
#include <cuda_runtime.h>
#include <cuda_bf16.h>
#include <cstdint>

// ---------------- problem shape constants ----------------
#define CHUNKS 27      // K3 neighbors = 27 K-chunks of 64
#define CIN    64
#define COUT   128
#define TM     64      // rows per CTA
#define NTHR   512     // 16 warps: 4 n32-blocks x 4 k16-steps

// A smem: 2 buffers x [hi 64x144B | lo 64x144B]
#define A_ROW   144
#define A_HALF  (64 * A_ROW)        // 9216
#define A_BUF   (2 * A_HALF)        // 18432

// B fragment images: [27][4 ks][8 n16blk][32 lanes] x uint4, hi and lo
#define BFRAG_N (CHUNKS * 4 * 8 * 32)
__device__ __align__(16) uint4 g_BfragHi[BFRAG_N];
__device__ __align__(16) uint4 g_BfragLo[BFRAG_N];

// ---------------- asm helpers ----------------
__device__ __forceinline__ uint32_t smem_u32(const void* p) {
    return (uint32_t)__cvta_generic_to_shared(p);
}
__device__ __forceinline__ void sts128(uint32_t addr, const uint32_t* r) {
    asm volatile("st.shared.v4.b32 [%0], {%1,%2,%3,%4};"
                 :: "r"(addr), "r"(r[0]), "r"(r[1]), "r"(r[2]), "r"(r[3]) : "memory");
}
__device__ __forceinline__ void ldsm4(uint32_t* r, uint32_t addr) {
    asm volatile("ldmatrix.sync.aligned.m8n8.x4.shared.b16 {%0,%1,%2,%3}, [%4];"
                 : "=r"(r[0]), "=r"(r[1]), "=r"(r[2]), "=r"(r[3]) : "r"(addr));
}
__device__ __forceinline__ void mma16816(float* d, const uint32_t* a, const uint32_t* b) {
    asm volatile(
        "mma.sync.aligned.m16n8k16.row.col.f32.bf16.bf16.f32 "
        "{%0,%1,%2,%3}, {%4,%5,%6,%7}, {%8,%9}, {%0,%1,%2,%3};"
        : "+f"(d[0]), "+f"(d[1]), "+f"(d[2]), "+f"(d[3])
        : "r"(a[0]), "r"(a[1]), "r"(a[2]), "r"(a[3]), "r"(b[0]), "r"(b[1]));
}
__device__ __forceinline__ uint32_t pack_hi(float v0, float v1) {
    return __byte_perm(__float_as_uint(v0), __float_as_uint(v1), 0x7632);
}
__device__ __forceinline__ uint32_t pack_lo(float v0, float v1) {
    float h0 = __uint_as_float(__float_as_uint(v0) & 0xFFFF0000u);
    float h1 = __uint_as_float(__float_as_uint(v1) & 0xFFFF0000u);
    float l0 = v0 - h0, l1 = v1 - h1;
    uint32_t r;
    asm("cvt.rn.bf16x2.f32 %0, %1, %2;" : "=r"(r) : "f"(l1), "f"(l0));
    return r;
}

// =============================================================================
// Prep: W -> bf16 hi/lo images in exact mma B-fragment order (unchanged).
// Entry e = ((c*4+ks)*8 + t)*32 + l
// =============================================================================
__global__ void prep_b_kernel(const float* __restrict__ W) {
    int e = blockIdx.x * blockDim.x + threadIdx.x;
    if (e >= BFRAG_N) return;
    int l  = e & 31;
    int t  = (e >> 5) & 7;
    int ks = (e >> 8) & 3;
    int c  = e >> 10;
    int r = l & 3, ncol = l >> 2;
    int n0 = t * 16 + ncol, n1 = n0 + 8;
    int kb = ks * 16 + 2 * r;
    const float* Wc = W + (size_t)c * CIN * COUT;
    float v0 = Wc[(size_t)(kb + 0) * COUT + n0];
    float v1 = Wc[(size_t)(kb + 1) * COUT + n0];
    float v2 = Wc[(size_t)(kb + 8) * COUT + n0];
    float v3 = Wc[(size_t)(kb + 9) * COUT + n0];
    float v4 = Wc[(size_t)(kb + 0) * COUT + n1];
    float v5 = Wc[(size_t)(kb + 1) * COUT + n1];
    float v6 = Wc[(size_t)(kb + 8) * COUT + n1];
    float v7 = Wc[(size_t)(kb + 9) * COUT + n1];
    uint4 hi, lo;
    hi.x = pack_hi(v0, v1); hi.y = pack_hi(v2, v3);
    hi.z = pack_hi(v4, v5); hi.w = pack_hi(v6, v7);
    lo.x = pack_lo(v0, v1); lo.y = pack_lo(v2, v3);
    lo.z = pack_lo(v4, v5); lo.w = pack_lo(v6, v7);
    g_BfragHi[e] = hi;
    g_BfragLo[e] = lo;
}

// =============================================================================
// Fused kernel. 16 warps: wk = wid&3 (k16 step), wn = wid>>2 (n32 block).
// Warp tile m64 x n32 x k16 -> A-ldsm redundancy 4x (was 8x), B read once.
// K partials merged across the 4 wk-warps before LN.
// =============================================================================
__global__ __launch_bounds__(NTHR)
void fused_mma_kernel(const float* __restrict__ features,
                      const float* __restrict__ center,
                      const int* __restrict__ voxel_idx,
                      const int* __restrict__ num_list,
                      const float* __restrict__ gamma,
                      const float* __restrict__ beta,
                      float* __restrict__ outF,
                      float* __restrict__ outC,
                      int N, int M, int B, int K, int BK)
{
    __shared__ __align__(16) unsigned char sA[A_BUF * 2];   // 36864; overlaid by merge buf
    __shared__ int    sIdx[TM * CHUNKS];
    __shared__ int    sSrc[TM];
    __shared__ int    sVal[TM];
    __shared__ float2 sRed[TM * 4];

    const uint32_t sAb = smem_u32(sA);
    const int tid = threadIdx.x;
    const int r0  = blockIdx.x * TM;

    // ---- bookkeeping + coords (tid < 64) ----
    if (tid < TM) {
        int g = r0 + tid;
        int valid = 0, srcRow = 0, b = 0;
        if (g < BK) {
            b = g / K;
            int j = g - b * K;
            int off = 0;
            for (int bb = 0; bb < b; bb++) off += num_list[bb];
            int nl = num_list[b];
            int end = nl < K ? nl : K;
            valid = (j < end) ? 1 : 0;
            long long s = (long long)off + j;
            if (s < 0) s = 0;
            if (s > (long long)(M - 1)) s = M - 1;
            srcRow = (int)s;
        }
        sVal[tid] = valid;
        sSrc[tid] = srcRow;
        if (g < BK) {
            float c0 = (b < B - 1) ? (float)(b + 1) : 0.0f;
            float x = 0.f, y = 0.f, z = 0.f;
            if (valid) {
                x = center[(size_t)srcRow * 3 + 0];
                y = center[(size_t)srcRow * 3 + 1];
                z = center[(size_t)srcRow * 3 + 2];
            }
            *(float4*)(outC + (size_t)g * 4) = make_float4(c0, x, y, z);
        }
    }
    __syncthreads();

    // ---- stage neighbor indices ----
    for (int e = tid; e < TM * CHUNKS; e += NTHR) {
        int m = e / CHUNKS, c = e - m * CHUNKS;
        int v = voxel_idx[(size_t)sSrc[m] * CHUNKS + c];
        sIdx[e] = (v < 0) ? -1 : (v > N - 1 ? N - 1 : v);
    }
    __syncthreads();

    // producer mapping: row m, 8 channels (q*8..q*8+7)
    const int m = tid >> 3, q = tid & 7;
    // consumer mapping: wk = k16 step, wn = n32 block
    const int l   = tid & 31;
    const int wid = tid >> 5;        // 0..15
    const int wk  = wid & 3;
    const int wn  = wid >> 2;
    const uint32_t aOffBase = (uint32_t)((l & 15) * A_ROW + ((l >> 4) << 4));
    // B entry for (chunk c): e = ((c*4 + wk)*8 + 2*wn)*32 + l ; t+1 -> +32
    const uint32_t bIdxBase = (uint32_t)((2 * wn) * 32 + l);

    float acc[4][4][4];   // [f: m16 blk][j: n8 blk within n32][regs]
    #pragma unroll
    for (int f = 0; f < 4; f++)
        #pragma unroll
        for (int j = 0; j < 4; j++)
            #pragma unroll
            for (int i = 0; i < 4; i++) acc[f][j][i] = 0.0f;

    auto gatherA = [&](int c, float4* fa) {
        int idx = sIdx[m * CHUNKS + c];
        if (idx >= 0) {
            const float4* p = (const float4*)features + (size_t)idx * 16 + q * 2;
            fa[0] = p[0];
            fa[1] = p[1];
        } else {
            fa[0] = make_float4(0.f, 0.f, 0.f, 0.f);
            fa[1] = make_float4(0.f, 0.f, 0.f, 0.f);
        }
    };
    auto loadB = [&](int c, uint4 (&Bh)[2], uint4 (&Bl)[2]) {
        const uint4* bh = g_BfragHi + ((size_t)(c * 4 + wk) * 8) * 32 + bIdxBase;
        const uint4* bl = g_BfragLo + ((size_t)(c * 4 + wk) * 8) * 32 + bIdxBase;
        Bh[0] = bh[0];  Bh[1] = bh[32];
        Bl[0] = bl[0];  Bl[1] = bl[32];
    };
    auto convertStoreA = [&](const float4* fa, int abuf) {
        uint32_t hi[4], lo[4];
        const float* ff = (const float*)fa;
        #pragma unroll
        for (int i = 0; i < 4; i++) {
            hi[i] = pack_hi(ff[2 * i], ff[2 * i + 1]);
            lo[i] = pack_lo(ff[2 * i], ff[2 * i + 1]);
        }
        uint32_t aB = sAb + abuf * A_BUF + m * A_ROW + q * 16;
        sts128(aB,          hi);
        sts128(aB + A_HALF, lo);
    };

    uint4 B0h[2], B0l[2], B1h[2], B1l[2];
    float4 fa[2];

    // ---- prologue ----
    loadB(0, B0h, B0l);
    gatherA(0, fa);
    convertStoreA(fa, 0);
    gatherA(1, fa);
    __syncthreads();

    auto step = [&](int c, uint4 (&BhC)[2], uint4 (&BlC)[2],
                    uint4 (&BhN)[2], uint4 (&BlN)[2]) {
        if (c + 1 < CHUNKS) loadB(c + 1, BhN, BlN);

        const uint32_t aBase = sAb + (c & 1) * A_BUF + aOffBase + wk * 32;
        uint32_t ah[4][4], al[4][4];
        #pragma unroll
        for (int f = 0; f < 4; f++) {
            ldsm4(ah[f], aBase + f * 16 * A_ROW);
            ldsm4(al[f], aBase + A_HALF + f * 16 * A_ROW);
        }
        #pragma unroll
        for (int f = 0; f < 4; f++) {
            #pragma unroll
            for (int t = 0; t < 2; t++) {
                const uint32_t* bh = (const uint32_t*)&BhC[t];
                const uint32_t* bl = (const uint32_t*)&BlC[t];
                #pragma unroll
                for (int g = 0; g < 2; g++) {
                    float* a = acc[f][t * 2 + g];
                    mma16816(a, ah[f], bh + g * 2);   // hi*hi
                    mma16816(a, ah[f], bl + g * 2);   // hi*lo
                    mma16816(a, al[f], bh + g * 2);   // lo*hi
                }
            }
        }

        if (c + 1 < CHUNKS) {
            convertStoreA(fa, (c + 1) & 1);
            if (c + 2 < CHUNKS) gatherA(c + 2, fa);
        }
        __syncthreads();
    };

    #pragma unroll 1
    for (int c = 0; c < CHUNKS - 1; c += 2) {
        step(c,     B0h, B0l, B1h, B1l);
        step(c + 1, B1h, B1l, B0h, B0l);
    }
    step(CHUNKS - 1, B0h, B0l, B1h, B1l);

    // ---- merge K partials across wk=1..3 into wk=0 (per f to bound smem) ----
    // overlay on sA: [12 slots][32 lanes][16 floats] = 24576 B
    float* sM = (float*)sA;
    #pragma unroll 1
    for (int f = 0; f < 4; f++) {
        if (wk > 0) {
            float* dst = sM + (((wk - 1) * 4 + wn) * 32 + l) * 16;
            #pragma unroll
            for (int j = 0; j < 4; j++)
                #pragma unroll
                for (int i = 0; i < 4; i++) dst[j * 4 + i] = acc[f][j][i];
        }
        __syncthreads();
        if (wk == 0) {
            #pragma unroll
            for (int s = 0; s < 3; s++) {
                const float* src = sM + ((s * 4 + wn) * 32 + l) * 16;
                #pragma unroll
                for (int j = 0; j < 4; j++)
                    #pragma unroll
                    for (int i = 0; i < 4; i++) acc[f][j][i] += src[j * 4 + i];
            }
        }
        __syncthreads();
    }

    // ---- LN stats (wk==0 warps hold full-K acc) ----
    if (wk == 0) {
        #pragma unroll
        for (int f = 0; f < 4; f++) {
            #pragma unroll
            for (int h = 0; h < 2; h++) {
                float s = 0.f, sq = 0.f;
                #pragma unroll
                for (int j = 0; j < 4; j++) {
                    float v0 = acc[f][j][h * 2], v1 = acc[f][j][h * 2 + 1];
                    s += v0 + v1;
                    sq += v0 * v0 + v1 * v1;
                }
                s  += __shfl_xor_sync(0xffffffffu, s, 1);
                sq += __shfl_xor_sync(0xffffffffu, sq, 1);
                s  += __shfl_xor_sync(0xffffffffu, s, 2);
                sq += __shfl_xor_sync(0xffffffffu, sq, 2);
                if ((l & 3) == 0) {
                    int R = f * 16 + h * 8 + (l >> 2);
                    sRed[R * 4 + wn] = make_float2(s, sq);
                }
            }
        }
    }
    __syncthreads();

    if (wk == 0) {
        const float invC = 1.0f / (float)COUT;
        #pragma unroll
        for (int f = 0; f < 4; f++) {
            #pragma unroll
            for (int h = 0; h < 2; h++) {
                int R = f * 16 + h * 8 + (l >> 2);
                float2 p0 = sRed[R * 4 + 0], p1 = sRed[R * 4 + 1];
                float2 p2 = sRed[R * 4 + 2], p3 = sRed[R * 4 + 3];
                float st  = p0.x + p1.x + p2.x + p3.x;
                float sqt = p0.y + p1.y + p2.y + p3.y;
                float mu  = st * invC;
                float var = sqt * invC - mu * mu;
                float rs  = rsqrtf(var + 1e-3f);
                int valid = sVal[R];
                int grow  = r0 + R;
                if (grow < BK) {
                    float* op = outF + (size_t)grow * COUT;
                    #pragma unroll
                    for (int j = 0; j < 4; j++) {
                        int C = wn * 32 + (j >> 1) * 16 + (j & 1) * 8 + (l & 3) * 2;
                        float2 gm = *(const float2*)(gamma + C);
                        float2 bt = *(const float2*)(beta + C);
                        float v0 = acc[f][j][h * 2], v1 = acc[f][j][h * 2 + 1];
                        float2 o;
                        o.x = valid ? fmaxf((v0 - mu) * rs * gm.x + bt.x, 0.f) : 0.f;
                        o.y = valid ? fmaxf((v1 - mu) * rs * gm.y + bt.y, 0.f) : 0.f;
                        *(float2*)(op + C) = o;
                    }
                }
            }
        }
    }
}

// =============================================================================
extern "C" void kernel_launch(void* const* d_in, const int* in_sizes, int n_in,
                              void* d_out, int out_size)
{
    const float* features = (const float*)d_in[0];
    const float* center   = (const float*)d_in[1];
    const int*   voxel    = (const int*)d_in[2];     // int32 (JAX x64 disabled)
    const int*   num_list = (const int*)d_in[3];
    const float* W        = (const float*)d_in[4];
    const float* gamma    = (const float*)d_in[5];
    const float* beta     = (const float*)d_in[6];

    int B    = in_sizes[3];
    int Cout = in_sizes[5];
    int M    = in_sizes[1] / 3;
    int K3r  = in_sizes[2] / M;
    int Cin  = in_sizes[4] / (K3r * Cout);
    int N    = in_sizes[0] / Cin;
    int K    = out_size / (B * (Cout + 4));
    int BK   = B * K;

    float* out  = (float*)d_out;
    float* outC = out + (size_t)BK * Cout;

    prep_b_kernel<<<(BFRAG_N + 255) / 256, 256>>>(W);

    int grid = (BK + TM - 1) / TM;
    fused_mma_kernel<<<grid, NTHR>>>(
        features, center, voxel, num_list, gamma, beta, out, outC,
        N, M, B, K, BK);
}

// round 13
// speedup vs baseline: 1.3367x; 1.3367x over previous
#include <cuda_runtime.h>
#include <cuda_bf16.h>
#include <cstdint>

// ---------------- problem shape constants ----------------
#define CHUNKS 27      // K3 neighbors = 27 K-chunks of 64
#define CIN    64
#define COUT   128
#define TM     64      // rows per CTA
#define NTHR   512     // 16 warps: 2M x 4N x 2K, warp tile m32 x n32 x k32

// A smem: 2 buffers x [hi 64x144B | lo 64x144B]
#define A_ROW   144
#define A_HALF  (64 * A_ROW)        // 9216
#define A_BUF   (2 * A_HALF)        // 18432

// B fragment images: [27][4 ks][8 n16blk][32 lanes] x uint4, hi and lo
#define BFRAG_N (CHUNKS * 4 * 8 * 32)
__device__ __align__(16) uint4 g_BfragHi[BFRAG_N];
__device__ __align__(16) uint4 g_BfragLo[BFRAG_N];

// ---------------- asm helpers ----------------
__device__ __forceinline__ uint32_t smem_u32(const void* p) {
    return (uint32_t)__cvta_generic_to_shared(p);
}
__device__ __forceinline__ void sts128(uint32_t addr, const uint32_t* r) {
    asm volatile("st.shared.v4.b32 [%0], {%1,%2,%3,%4};"
                 :: "r"(addr), "r"(r[0]), "r"(r[1]), "r"(r[2]), "r"(r[3]) : "memory");
}
__device__ __forceinline__ void ldsm4(uint32_t* r, uint32_t addr) {
    asm volatile("ldmatrix.sync.aligned.m8n8.x4.shared.b16 {%0,%1,%2,%3}, [%4];"
                 : "=r"(r[0]), "=r"(r[1]), "=r"(r[2]), "=r"(r[3]) : "r"(addr));
}
__device__ __forceinline__ void mma16816(float* d, const uint32_t* a, const uint32_t* b) {
    asm volatile(
        "mma.sync.aligned.m16n8k16.row.col.f32.bf16.bf16.f32 "
        "{%0,%1,%2,%3}, {%4,%5,%6,%7}, {%8,%9}, {%0,%1,%2,%3};"
        : "+f"(d[0]), "+f"(d[1]), "+f"(d[2]), "+f"(d[3])
        : "r"(a[0]), "r"(a[1]), "r"(a[2]), "r"(a[3]), "r"(b[0]), "r"(b[1]));
}
__device__ __forceinline__ uint32_t pack_hi(float v0, float v1) {
    return __byte_perm(__float_as_uint(v0), __float_as_uint(v1), 0x7632);
}
__device__ __forceinline__ uint32_t pack_lo(float v0, float v1) {
    float h0 = __uint_as_float(__float_as_uint(v0) & 0xFFFF0000u);
    float h1 = __uint_as_float(__float_as_uint(v1) & 0xFFFF0000u);
    float l0 = v0 - h0, l1 = v1 - h1;
    uint32_t r;
    asm("cvt.rn.bf16x2.f32 %0, %1, %2;" : "=r"(r) : "f"(l1), "f"(l0));
    return r;
}

// =============================================================================
// Prep: W -> bf16 hi/lo images in exact mma B-fragment order (unchanged).
// Entry e = ((c*4+ks)*8 + t)*32 + l
// =============================================================================
__global__ void prep_b_kernel(const float* __restrict__ W) {
    int e = blockIdx.x * blockDim.x + threadIdx.x;
    if (e >= BFRAG_N) return;
    int l  = e & 31;
    int t  = (e >> 5) & 7;
    int ks = (e >> 8) & 3;
    int c  = e >> 10;
    int r = l & 3, ncol = l >> 2;
    int n0 = t * 16 + ncol, n1 = n0 + 8;
    int kb = ks * 16 + 2 * r;
    const float* Wc = W + (size_t)c * CIN * COUT;
    float v0 = Wc[(size_t)(kb + 0) * COUT + n0];
    float v1 = Wc[(size_t)(kb + 1) * COUT + n0];
    float v2 = Wc[(size_t)(kb + 8) * COUT + n0];
    float v3 = Wc[(size_t)(kb + 9) * COUT + n0];
    float v4 = Wc[(size_t)(kb + 0) * COUT + n1];
    float v5 = Wc[(size_t)(kb + 1) * COUT + n1];
    float v6 = Wc[(size_t)(kb + 8) * COUT + n1];
    float v7 = Wc[(size_t)(kb + 9) * COUT + n1];
    uint4 hi, lo;
    hi.x = pack_hi(v0, v1); hi.y = pack_hi(v2, v3);
    hi.z = pack_hi(v4, v5); hi.w = pack_hi(v6, v7);
    lo.x = pack_lo(v0, v1); lo.y = pack_lo(v2, v3);
    lo.z = pack_lo(v4, v5); lo.w = pack_lo(v6, v7);
    g_BfragHi[e] = hi;
    g_BfragLo[e] = lo;
}

// =============================================================================
// Fused kernel. 16 warps: wk = wid&1 (k32 half), wm = (wid>>1)&1 (m32 half),
// wn = wid>>2 (n32 block). Warp tile m32 x n32 x k32:
//   acc = 32 regs, A-ldsm redundancy 4x, B phase-pipelined at half-chunk grain.
// =============================================================================
__global__ __launch_bounds__(NTHR)
void fused_mma_kernel(const float* __restrict__ features,
                      const float* __restrict__ center,
                      const int* __restrict__ voxel_idx,
                      const int* __restrict__ num_list,
                      const float* __restrict__ gamma,
                      const float* __restrict__ beta,
                      float* __restrict__ outF,
                      float* __restrict__ outC,
                      int N, int M, int B, int K, int BK)
{
    __shared__ __align__(16) unsigned char sA[A_BUF * 2];   // 36864; overlaid by merge buf
    __shared__ int    sIdx[TM * CHUNKS];
    __shared__ int    sSrc[TM];
    __shared__ int    sVal[TM];
    __shared__ float2 sRed[TM * 4];

    const uint32_t sAb = smem_u32(sA);
    const int tid = threadIdx.x;
    const int r0  = blockIdx.x * TM;

    // ---- bookkeeping + coords (tid < 64) ----
    if (tid < TM) {
        int g = r0 + tid;
        int valid = 0, srcRow = 0, b = 0;
        if (g < BK) {
            b = g / K;
            int j = g - b * K;
            int off = 0;
            for (int bb = 0; bb < b; bb++) off += num_list[bb];
            int nl = num_list[b];
            int end = nl < K ? nl : K;
            valid = (j < end) ? 1 : 0;
            long long s = (long long)off + j;
            if (s < 0) s = 0;
            if (s > (long long)(M - 1)) s = M - 1;
            srcRow = (int)s;
        }
        sVal[tid] = valid;
        sSrc[tid] = srcRow;
        if (g < BK) {
            float c0 = (b < B - 1) ? (float)(b + 1) : 0.0f;
            float x = 0.f, y = 0.f, z = 0.f;
            if (valid) {
                x = center[(size_t)srcRow * 3 + 0];
                y = center[(size_t)srcRow * 3 + 1];
                z = center[(size_t)srcRow * 3 + 2];
            }
            *(float4*)(outC + (size_t)g * 4) = make_float4(c0, x, y, z);
        }
    }
    __syncthreads();

    // ---- stage neighbor indices ----
    for (int e = tid; e < TM * CHUNKS; e += NTHR) {
        int m = e / CHUNKS, c = e - m * CHUNKS;
        int v = voxel_idx[(size_t)sSrc[m] * CHUNKS + c];
        sIdx[e] = (v < 0) ? -1 : (v > N - 1 ? N - 1 : v);
    }
    __syncthreads();

    // producer mapping: row m, 8 channels (q*8..q*8+7)
    const int m = tid >> 3, q = tid & 7;
    // consumer mapping
    const int l   = tid & 31;
    const int wid = tid >> 5;          // 0..15
    const int wk  = wid & 1;           // k32 half: ks in {2wk, 2wk+1}
    const int wm  = (wid >> 1) & 1;    // m32 half
    const int wn  = wid >> 2;          // n32 block 0..3
    const uint32_t aOffBase =
        (uint32_t)((wm * 32 + (l & 15)) * A_ROW + ((l >> 4) << 4));

    float acc[2][2][2][4];   // [f m16][tt n16][g n8][4 regs]
    #pragma unroll
    for (int f = 0; f < 2; f++)
        #pragma unroll
        for (int t = 0; t < 2; t++)
            #pragma unroll
            for (int g = 0; g < 2; g++)
                #pragma unroll
                for (int i = 0; i < 4; i++) acc[f][t][g][i] = 0.0f;

    auto gatherA = [&](int c, float4* fa) {
        int idx = sIdx[m * CHUNKS + c];
        if (idx >= 0) {
            const float4* p = (const float4*)features + (size_t)idx * 16 + q * 2;
            fa[0] = p[0];
            fa[1] = p[1];
        } else {
            fa[0] = make_float4(0.f, 0.f, 0.f, 0.f);
            fa[1] = make_float4(0.f, 0.f, 0.f, 0.f);
        }
    };
    // B for one phase (c, ks2): 2 n16 blocks (hi+lo) = 4 uint4
    auto loadB = [&](int c, int ks2, uint4 (&Bh)[2], uint4 (&Bl)[2]) {
        size_t base = ((size_t)(c * 4 + 2 * wk + ks2) * 8 + 2 * wn) * 32 + l;
        Bh[0] = g_BfragHi[base];       Bh[1] = g_BfragHi[base + 32];
        Bl[0] = g_BfragLo[base];       Bl[1] = g_BfragLo[base + 32];
    };
    auto convertStoreA = [&](const float4* fa, int abuf) {
        uint32_t hi[4], lo[4];
        const float* ff = (const float*)fa;
        #pragma unroll
        for (int i = 0; i < 4; i++) {
            hi[i] = pack_hi(ff[2 * i], ff[2 * i + 1]);
            lo[i] = pack_lo(ff[2 * i], ff[2 * i + 1]);
        }
        uint32_t aB = sAb + abuf * A_BUF + m * A_ROW + q * 16;
        sts128(aB,          hi);
        sts128(aB + A_HALF, lo);
    };
    // one mma phase: ks = 2wk + ks2 on A buffer of chunk c
    auto phase = [&](int c, int ks2, uint4 (&Bh)[2], uint4 (&Bl)[2]) {
        const int ks = 2 * wk + ks2;
        const uint32_t aBase = sAb + (c & 1) * A_BUF + aOffBase + ks * 32;
        #pragma unroll
        for (int f = 0; f < 2; f++) {
            uint32_t ah[4], al[4];
            ldsm4(ah, aBase + f * 16 * A_ROW);
            ldsm4(al, aBase + A_HALF + f * 16 * A_ROW);
            #pragma unroll
            for (int t = 0; t < 2; t++) {
                const uint32_t* bh = (const uint32_t*)&Bh[t];
                const uint32_t* bl = (const uint32_t*)&Bl[t];
                #pragma unroll
                for (int g = 0; g < 2; g++) {
                    float* a = acc[f][t][g];
                    mma16816(a, ah, bh + g * 2);   // hi*hi
                    mma16816(a, ah, bl + g * 2);   // hi*lo
                    mma16816(a, al, bh + g * 2);   // lo*hi
                }
            }
        }
    };

    uint4 P0h[2], P0l[2], P1h[2], P1l[2];
    float4 fa[2];

    // ---- prologue: B(0, ks2=0), A(0) staged, fa holds A(1) ----
    loadB(0, 0, P0h, P0l);
    gatherA(0, fa);
    convertStoreA(fa, 0);
    gatherA(1, fa);
    __syncthreads();

    #pragma unroll 1
    for (int c = 0; c < CHUNKS; c++) {
        loadB(c, 1, P1h, P1l);                     // B for phase (c,1)
        phase(c, 0, P0h, P0l);
        if (c + 1 < CHUNKS) loadB(c + 1, 0, P0h, P0l);   // B for next chunk ph0
        phase(c, 1, P1h, P1l);
        if (c + 1 < CHUNKS) {
            convertStoreA(fa, (c + 1) & 1);
            if (c + 2 < CHUNKS) gatherA(c + 2, fa);
        }
        __syncthreads();
    }

    // ---- merge K partials: wk=1 -> smem, wk=0 adds ----
    float* sM = (float*)sA;     // [8 su][32 lanes][stride 33] = 33792 B
    const int su = wid >> 1;    // 0..7 shared by the wk pair
    if (wk == 1) {
        float* dst = sM + ((size_t)su * 32 + l) * 33;
        #pragma unroll
        for (int f = 0; f < 2; f++)
            #pragma unroll
            for (int t = 0; t < 2; t++)
                #pragma unroll
                for (int g = 0; g < 2; g++)
                    #pragma unroll
                    for (int i = 0; i < 4; i++)
                        dst[((f * 2 + t) * 2 + g) * 4 + i] = acc[f][t][g][i];
    }
    __syncthreads();
    if (wk == 0) {
        const float* src = sM + ((size_t)su * 32 + l) * 33;
        #pragma unroll
        for (int f = 0; f < 2; f++)
            #pragma unroll
            for (int t = 0; t < 2; t++)
                #pragma unroll
                for (int g = 0; g < 2; g++)
                    #pragma unroll
                    for (int i = 0; i < 4; i++)
                        acc[f][t][g][i] += src[((f * 2 + t) * 2 + g) * 4 + i];

        // LN partial stats: rows wm*32 + f*16 + h*8 + (l>>2), cols n32 of wn
        #pragma unroll
        for (int f = 0; f < 2; f++) {
            #pragma unroll
            for (int h = 0; h < 2; h++) {
                float s = 0.f, sq = 0.f;
                #pragma unroll
                for (int t = 0; t < 2; t++)
                    #pragma unroll
                    for (int g = 0; g < 2; g++) {
                        float v0 = acc[f][t][g][h * 2], v1 = acc[f][t][g][h * 2 + 1];
                        s += v0 + v1;
                        sq += v0 * v0 + v1 * v1;
                    }
                s  += __shfl_xor_sync(0xffffffffu, s, 1);
                sq += __shfl_xor_sync(0xffffffffu, sq, 1);
                s  += __shfl_xor_sync(0xffffffffu, s, 2);
                sq += __shfl_xor_sync(0xffffffffu, sq, 2);
                if ((l & 3) == 0) {
                    int R = wm * 32 + f * 16 + h * 8 + (l >> 2);
                    sRed[R * 4 + wn] = make_float2(s, sq);
                }
            }
        }
    }
    __syncthreads();

    if (wk == 0) {
        const float invC = 1.0f / (float)COUT;
        #pragma unroll
        for (int f = 0; f < 2; f++) {
            #pragma unroll
            for (int h = 0; h < 2; h++) {
                int R = wm * 32 + f * 16 + h * 8 + (l >> 2);
                float2 p0 = sRed[R * 4 + 0], p1 = sRed[R * 4 + 1];
                float2 p2 = sRed[R * 4 + 2], p3 = sRed[R * 4 + 3];
                float st  = p0.x + p1.x + p2.x + p3.x;
                float sqt = p0.y + p1.y + p2.y + p3.y;
                float mu  = st * invC;
                float var = sqt * invC - mu * mu;
                float rs  = rsqrtf(var + 1e-3f);
                int valid = sVal[R];
                int grow  = r0 + R;
                if (grow < BK) {
                    float* op = outF + (size_t)grow * COUT;
                    #pragma unroll
                    for (int t = 0; t < 2; t++) {
                        #pragma unroll
                        for (int g = 0; g < 2; g++) {
                            int C = wn * 32 + t * 16 + g * 8 + (l & 3) * 2;
                            float2 gm = *(const float2*)(gamma + C);
                            float2 bt = *(const float2*)(beta + C);
                            float v0 = acc[f][t][g][h * 2];
                            float v1 = acc[f][t][g][h * 2 + 1];
                            float2 o;
                            o.x = valid ? fmaxf((v0 - mu) * rs * gm.x + bt.x, 0.f) : 0.f;
                            o.y = valid ? fmaxf((v1 - mu) * rs * gm.y + bt.y, 0.f) : 0.f;
                            *(float2*)(op + C) = o;
                        }
                    }
                }
            }
        }
    }
}

// =============================================================================
extern "C" void kernel_launch(void* const* d_in, const int* in_sizes, int n_in,
                              void* d_out, int out_size)
{
    const float* features = (const float*)d_in[0];
    const float* center   = (const float*)d_in[1];
    const int*   voxel    = (const int*)d_in[2];     // int32 (JAX x64 disabled)
    const int*   num_list = (const int*)d_in[3];
    const float* W        = (const float*)d_in[4];
    const float* gamma    = (const float*)d_in[5];
    const float* beta     = (const float*)d_in[6];

    int B    = in_sizes[3];
    int Cout = in_sizes[5];
    int M    = in_sizes[1] / 3;
    int K3r  = in_sizes[2] / M;
    int Cin  = in_sizes[4] / (K3r * Cout);
    int N    = in_sizes[0] / Cin;
    int K    = out_size / (B * (Cout + 4));
    int BK   = B * K;

    float* out  = (float*)d_out;
    float* outC = out + (size_t)BK * Cout;

    prep_b_kernel<<<(BFRAG_N + 255) / 256, 256>>>(W);

    int grid = (BK + TM - 1) / TM;
    fused_mma_kernel<<<grid, NTHR>>>(
        features, center, voxel, num_list, gamma, beta, out, outC,
        N, M, B, K, BK);
}

// round 14
// speedup vs baseline: 1.4073x; 1.0528x over previous
#include <cuda_runtime.h>
#include <cuda_bf16.h>
#include <cstdint>

// ---------------- problem shape constants ----------------
#define CHUNKS 27      // K3 neighbors = 27 K-chunks of 64
#define CIN    64
#define COUT   128
#define TM     32      // rows per CTA (2 CTAs/SM for tensor-bubble overlap)
#define NTHR   256     // 8 warps: 4N x 2K, warp tile m32 x n32 x k32

// A smem: 2 buffers x [hi 32x144B | lo 32x144B]
#define A_ROW   144
#define A_HALF  (32 * A_ROW)        // 4608
#define A_BUF   (2 * A_HALF)        // 9216

// B fragment images: [27][4 ks][8 n16blk][32 lanes] x uint4, hi and lo
#define BFRAG_N (CHUNKS * 4 * 8 * 32)
__device__ __align__(16) uint4 g_BfragHi[BFRAG_N];
__device__ __align__(16) uint4 g_BfragLo[BFRAG_N];

// ---------------- asm helpers ----------------
__device__ __forceinline__ uint32_t smem_u32(const void* p) {
    return (uint32_t)__cvta_generic_to_shared(p);
}
__device__ __forceinline__ void sts128(uint32_t addr, const uint32_t* r) {
    asm volatile("st.shared.v4.b32 [%0], {%1,%2,%3,%4};"
                 :: "r"(addr), "r"(r[0]), "r"(r[1]), "r"(r[2]), "r"(r[3]) : "memory");
}
__device__ __forceinline__ void ldsm4(uint32_t* r, uint32_t addr) {
    asm volatile("ldmatrix.sync.aligned.m8n8.x4.shared.b16 {%0,%1,%2,%3}, [%4];"
                 : "=r"(r[0]), "=r"(r[1]), "=r"(r[2]), "=r"(r[3]) : "r"(addr));
}
__device__ __forceinline__ void mma16816(float* d, const uint32_t* a, const uint32_t* b) {
    asm volatile(
        "mma.sync.aligned.m16n8k16.row.col.f32.bf16.bf16.f32 "
        "{%0,%1,%2,%3}, {%4,%5,%6,%7}, {%8,%9}, {%0,%1,%2,%3};"
        : "+f"(d[0]), "+f"(d[1]), "+f"(d[2]), "+f"(d[3])
        : "r"(a[0]), "r"(a[1]), "r"(a[2]), "r"(a[3]), "r"(b[0]), "r"(b[1]));
}
__device__ __forceinline__ uint32_t pack_hi(float v0, float v1) {
    return __byte_perm(__float_as_uint(v0), __float_as_uint(v1), 0x7632);
}
__device__ __forceinline__ uint32_t pack_lo(float v0, float v1) {
    float h0 = __uint_as_float(__float_as_uint(v0) & 0xFFFF0000u);
    float h1 = __uint_as_float(__float_as_uint(v1) & 0xFFFF0000u);
    float l0 = v0 - h0, l1 = v1 - h1;
    uint32_t r;
    asm("cvt.rn.bf16x2.f32 %0, %1, %2;" : "=r"(r) : "f"(l1), "f"(l0));
    return r;
}

// =============================================================================
// Prep: W -> bf16 hi/lo images in exact mma B-fragment order (unchanged).
// Entry e = ((c*4+ks)*8 + t)*32 + l
// =============================================================================
__global__ void prep_b_kernel(const float* __restrict__ W) {
    int e = blockIdx.x * blockDim.x + threadIdx.x;
    if (e >= BFRAG_N) return;
    int l  = e & 31;
    int t  = (e >> 5) & 7;
    int ks = (e >> 8) & 3;
    int c  = e >> 10;
    int r = l & 3, ncol = l >> 2;
    int n0 = t * 16 + ncol, n1 = n0 + 8;
    int kb = ks * 16 + 2 * r;
    const float* Wc = W + (size_t)c * CIN * COUT;
    float v0 = Wc[(size_t)(kb + 0) * COUT + n0];
    float v1 = Wc[(size_t)(kb + 1) * COUT + n0];
    float v2 = Wc[(size_t)(kb + 8) * COUT + n0];
    float v3 = Wc[(size_t)(kb + 9) * COUT + n0];
    float v4 = Wc[(size_t)(kb + 0) * COUT + n1];
    float v5 = Wc[(size_t)(kb + 1) * COUT + n1];
    float v6 = Wc[(size_t)(kb + 8) * COUT + n1];
    float v7 = Wc[(size_t)(kb + 9) * COUT + n1];
    uint4 hi, lo;
    hi.x = pack_hi(v0, v1); hi.y = pack_hi(v2, v3);
    hi.z = pack_hi(v4, v5); hi.w = pack_hi(v6, v7);
    lo.x = pack_lo(v0, v1); lo.y = pack_lo(v2, v3);
    lo.z = pack_lo(v4, v5); lo.w = pack_lo(v6, v7);
    g_BfragHi[e] = hi;
    g_BfragLo[e] = lo;
}

// =============================================================================
// Fused kernel. 8 warps: wk = wid&1 (k32 half), wn = wid>>1 (n32 block 0..3).
// Warp tile m32 x n32 x k32; acc = 32 regs. 2 CTAs/SM hide chunk-loop bubbles.
// =============================================================================
__global__ __launch_bounds__(NTHR, 2)
void fused_mma_kernel(const float* __restrict__ features,
                      const float* __restrict__ center,
                      const int* __restrict__ voxel_idx,
                      const int* __restrict__ num_list,
                      const float* __restrict__ gamma,
                      const float* __restrict__ beta,
                      float* __restrict__ outF,
                      float* __restrict__ outC,
                      int N, int M, int B, int K, int BK)
{
    __shared__ __align__(16) unsigned char sA[A_BUF * 2];   // 18432; overlaid by merge buf
    __shared__ int    sIdx[TM * CHUNKS];
    __shared__ int    sSrc[TM];
    __shared__ int    sVal[TM];
    __shared__ float2 sRed[TM * 4];

    const uint32_t sAb = smem_u32(sA);
    const int tid = threadIdx.x;
    const int r0  = blockIdx.x * TM;

    // ---- bookkeeping + coords (tid < 32) ----
    if (tid < TM) {
        int g = r0 + tid;
        int valid = 0, srcRow = 0, b = 0;
        if (g < BK) {
            b = g / K;
            int j = g - b * K;
            int off = 0;
            for (int bb = 0; bb < b; bb++) off += num_list[bb];
            int nl = num_list[b];
            int end = nl < K ? nl : K;
            valid = (j < end) ? 1 : 0;
            long long s = (long long)off + j;
            if (s < 0) s = 0;
            if (s > (long long)(M - 1)) s = M - 1;
            srcRow = (int)s;
        }
        sVal[tid] = valid;
        sSrc[tid] = srcRow;
        if (g < BK) {
            float c0 = (b < B - 1) ? (float)(b + 1) : 0.0f;
            float x = 0.f, y = 0.f, z = 0.f;
            if (valid) {
                x = center[(size_t)srcRow * 3 + 0];
                y = center[(size_t)srcRow * 3 + 1];
                z = center[(size_t)srcRow * 3 + 2];
            }
            *(float4*)(outC + (size_t)g * 4) = make_float4(c0, x, y, z);
        }
    }
    __syncthreads();

    // ---- stage neighbor indices ----
    for (int e = tid; e < TM * CHUNKS; e += NTHR) {
        int m = e / CHUNKS, c = e - m * CHUNKS;
        int v = voxel_idx[(size_t)sSrc[m] * CHUNKS + c];
        sIdx[e] = (v < 0) ? -1 : (v > N - 1 ? N - 1 : v);
    }
    __syncthreads();

    // producer mapping: row m (0..31), 8 channels (q*8..q*8+7)
    const int m = tid >> 3, q = tid & 7;
    // consumer mapping
    const int l   = tid & 31;
    const int wid = tid >> 5;          // 0..7
    const int wk  = wid & 1;           // k32 half: ks in {2wk, 2wk+1}
    const int wn  = wid >> 1;          // n32 block 0..3
    const uint32_t aOffBase = (uint32_t)((l & 15) * A_ROW + ((l >> 4) << 4));

    float acc[2][2][2][4];   // [f m16][t n16][g n8][4 regs]
    #pragma unroll
    for (int f = 0; f < 2; f++)
        #pragma unroll
        for (int t = 0; t < 2; t++)
            #pragma unroll
            for (int g = 0; g < 2; g++)
                #pragma unroll
                for (int i = 0; i < 4; i++) acc[f][t][g][i] = 0.0f;

    auto gatherA = [&](int c, float4* fa) {
        int idx = sIdx[m * CHUNKS + c];
        if (idx >= 0) {
            const float4* p = (const float4*)features + (size_t)idx * 16 + q * 2;
            fa[0] = p[0];
            fa[1] = p[1];
        } else {
            fa[0] = make_float4(0.f, 0.f, 0.f, 0.f);
            fa[1] = make_float4(0.f, 0.f, 0.f, 0.f);
        }
    };
    // B for one phase (c, ks2): 2 n16 blocks (hi+lo) = 4 uint4
    auto loadB = [&](int c, int ks2, uint4 (&Bh)[2], uint4 (&Bl)[2]) {
        size_t base = ((size_t)(c * 4 + 2 * wk + ks2) * 8 + 2 * wn) * 32 + l;
        Bh[0] = g_BfragHi[base];       Bh[1] = g_BfragHi[base + 32];
        Bl[0] = g_BfragLo[base];       Bl[1] = g_BfragLo[base + 32];
    };
    auto convertStoreA = [&](const float4* fa, int abuf) {
        uint32_t hi[4], lo[4];
        const float* ff = (const float*)fa;
        #pragma unroll
        for (int i = 0; i < 4; i++) {
            hi[i] = pack_hi(ff[2 * i], ff[2 * i + 1]);
            lo[i] = pack_lo(ff[2 * i], ff[2 * i + 1]);
        }
        uint32_t aB = sAb + abuf * A_BUF + m * A_ROW + q * 16;
        sts128(aB,          hi);
        sts128(aB + A_HALF, lo);
    };
    // one mma phase: ks = 2wk + ks2 on A buffer of chunk c
    auto phase = [&](int c, int ks2, uint4 (&Bh)[2], uint4 (&Bl)[2]) {
        const int ks = 2 * wk + ks2;
        const uint32_t aBase = sAb + (c & 1) * A_BUF + aOffBase + ks * 32;
        #pragma unroll
        for (int f = 0; f < 2; f++) {
            uint32_t ah[4], al[4];
            ldsm4(ah, aBase + f * 16 * A_ROW);
            ldsm4(al, aBase + A_HALF + f * 16 * A_ROW);
            #pragma unroll
            for (int t = 0; t < 2; t++) {
                const uint32_t* bh = (const uint32_t*)&Bh[t];
                const uint32_t* bl = (const uint32_t*)&Bl[t];
                #pragma unroll
                for (int g = 0; g < 2; g++) {
                    float* a = acc[f][t][g];
                    mma16816(a, ah, bh + g * 2);   // hi*hi
                    mma16816(a, ah, bl + g * 2);   // hi*lo
                    mma16816(a, al, bh + g * 2);   // lo*hi
                }
            }
        }
    };

    uint4 P0h[2], P0l[2], P1h[2], P1l[2];
    float4 fa[2];

    // ---- prologue: B(0, ks2=0), A(0) staged, fa holds A(1) ----
    loadB(0, 0, P0h, P0l);
    gatherA(0, fa);
    convertStoreA(fa, 0);
    gatherA(1, fa);
    __syncthreads();

    #pragma unroll 1
    for (int c = 0; c < CHUNKS; c++) {
        loadB(c, 1, P1h, P1l);                           // B for phase (c,1)
        phase(c, 0, P0h, P0l);
        if (c + 1 < CHUNKS) loadB(c + 1, 0, P0h, P0l);   // B for next chunk ph0
        phase(c, 1, P1h, P1l);
        if (c + 1 < CHUNKS) {
            convertStoreA(fa, (c + 1) & 1);
            if (c + 2 < CHUNKS) gatherA(c + 2, fa);
        }
        __syncthreads();
    }

    // ---- merge K partials: wk=1 -> smem, wk=0 adds ----
    float* sM = (float*)sA;     // [4 su][32 lanes][stride 33] = 16896 B
    const int su = wid >> 1;    // 0..3 shared by the wk pair
    if (wk == 1) {
        float* dst = sM + ((size_t)su * 32 + l) * 33;
        #pragma unroll
        for (int f = 0; f < 2; f++)
            #pragma unroll
            for (int t = 0; t < 2; t++)
                #pragma unroll
                for (int g = 0; g < 2; g++)
                    #pragma unroll
                    for (int i = 0; i < 4; i++)
                        dst[((f * 2 + t) * 2 + g) * 4 + i] = acc[f][t][g][i];
    }
    __syncthreads();
    if (wk == 0) {
        const float* src = sM + ((size_t)su * 32 + l) * 33;
        #pragma unroll
        for (int f = 0; f < 2; f++)
            #pragma unroll
            for (int t = 0; t < 2; t++)
                #pragma unroll
                for (int g = 0; g < 2; g++)
                    #pragma unroll
                    for (int i = 0; i < 4; i++)
                        acc[f][t][g][i] += src[((f * 2 + t) * 2 + g) * 4 + i];

        // LN partial stats: rows f*16 + h*8 + (l>>2), cols n32 of wn
        #pragma unroll
        for (int f = 0; f < 2; f++) {
            #pragma unroll
            for (int h = 0; h < 2; h++) {
                float s = 0.f, sq = 0.f;
                #pragma unroll
                for (int t = 0; t < 2; t++)
                    #pragma unroll
                    for (int g = 0; g < 2; g++) {
                        float v0 = acc[f][t][g][h * 2], v1 = acc[f][t][g][h * 2 + 1];
                        s += v0 + v1;
                        sq += v0 * v0 + v1 * v1;
                    }
                s  += __shfl_xor_sync(0xffffffffu, s, 1);
                sq += __shfl_xor_sync(0xffffffffu, sq, 1);
                s  += __shfl_xor_sync(0xffffffffu, s, 2);
                sq += __shfl_xor_sync(0xffffffffu, sq, 2);
                if ((l & 3) == 0) {
                    int R = f * 16 + h * 8 + (l >> 2);
                    sRed[R * 4 + wn] = make_float2(s, sq);
                }
            }
        }
    }
    __syncthreads();

    if (wk == 0) {
        const float invC = 1.0f / (float)COUT;
        #pragma unroll
        for (int f = 0; f < 2; f++) {
            #pragma unroll
            for (int h = 0; h < 2; h++) {
                int R = f * 16 + h * 8 + (l >> 2);
                float2 p0 = sRed[R * 4 + 0], p1 = sRed[R * 4 + 1];
                float2 p2 = sRed[R * 4 + 2], p3 = sRed[R * 4 + 3];
                float st  = p0.x + p1.x + p2.x + p3.x;
                float sqt = p0.y + p1.y + p2.y + p3.y;
                float mu  = st * invC;
                float var = sqt * invC - mu * mu;
                float rs  = rsqrtf(var + 1e-3f);
                int valid = sVal[R];
                int grow  = r0 + R;
                if (grow < BK) {
                    float* op = outF + (size_t)grow * COUT;
                    #pragma unroll
                    for (int t = 0; t < 2; t++) {
                        #pragma unroll
                        for (int g = 0; g < 2; g++) {
                            int C = wn * 32 + t * 16 + g * 8 + (l & 3) * 2;
                            float2 gm = *(const float2*)(gamma + C);
                            float2 bt = *(const float2*)(beta + C);
                            float v0 = acc[f][t][g][h * 2];
                            float v1 = acc[f][t][g][h * 2 + 1];
                            float2 o;
                            o.x = valid ? fmaxf((v0 - mu) * rs * gm.x + bt.x, 0.f) : 0.f;
                            o.y = valid ? fmaxf((v1 - mu) * rs * gm.y + bt.y, 0.f) : 0.f;
                            *(float2*)(op + C) = o;
                        }
                    }
                }
            }
        }
    }
}

// =============================================================================
extern "C" void kernel_launch(void* const* d_in, const int* in_sizes, int n_in,
                              void* d_out, int out_size)
{
    const float* features = (const float*)d_in[0];
    const float* center   = (const float*)d_in[1];
    const int*   voxel    = (const int*)d_in[2];     // int32 (JAX x64 disabled)
    const int*   num_list = (const int*)d_in[3];
    const float* W        = (const float*)d_in[4];
    const float* gamma    = (const float*)d_in[5];
    const float* beta     = (const float*)d_in[6];

    int B    = in_sizes[3];
    int Cout = in_sizes[5];
    int M    = in_sizes[1] / 3;
    int K3r  = in_sizes[2] / M;
    int Cin  = in_sizes[4] / (K3r * Cout);
    int N    = in_sizes[0] / Cin;
    int K    = out_size / (B * (Cout + 4));
    int BK   = B * K;

    float* out  = (float*)d_out;
    float* outC = out + (size_t)BK * Cout;

    prep_b_kernel<<<(BFRAG_N + 255) / 256, 256>>>(W);

    int grid = (BK + TM - 1) / TM;
    fused_mma_kernel<<<grid, NTHR>>>(
        features, center, voxel, num_list, gamma, beta, out, outC,
        N, M, B, K, BK);
}

// round 15
// speedup vs baseline: 1.7591x; 1.2500x over previous
#include <cuda_runtime.h>
#include <cuda_fp16.h>
#include <cstdint>

// ---------------- problem shape constants ----------------
#define CHUNKS 27      // K3 neighbors = 27 K-chunks of 64
#define CIN    64
#define COUT   128
#define TM     32      // rows per CTA (2 CTAs/SM)
#define NTHR   256     // 8 warps: 4N x 2K, warp tile m32 x n32 x k32

#define WSCALE    8192.0f
#define INV_WSCALE (1.0f / 8192.0f)

// A smem: 2 buffers x [hi 32x144B | lo 32x144B]
#define A_ROW   144
#define A_HALF  (32 * A_ROW)        // 4608
#define A_BUF   (2 * A_HALF)        // 9216

// B fragment image: [27][4 ks][8 n16blk][32 lanes] x uint4 (fp16 of 8192*W)
#define BFRAG_N (CHUNKS * 4 * 8 * 32)
__device__ __align__(16) uint4 g_Bfrag[BFRAG_N];

// ---------------- asm helpers ----------------
__device__ __forceinline__ uint32_t smem_u32(const void* p) {
    return (uint32_t)__cvta_generic_to_shared(p);
}
__device__ __forceinline__ void sts128(uint32_t addr, const uint32_t* r) {
    asm volatile("st.shared.v4.b32 [%0], {%1,%2,%3,%4};"
                 :: "r"(addr), "r"(r[0]), "r"(r[1]), "r"(r[2]), "r"(r[3]) : "memory");
}
__device__ __forceinline__ void ldsm4(uint32_t* r, uint32_t addr) {
    asm volatile("ldmatrix.sync.aligned.m8n8.x4.shared.b16 {%0,%1,%2,%3}, [%4];"
                 : "=r"(r[0]), "=r"(r[1]), "=r"(r[2]), "=r"(r[3]) : "r"(addr));
}
__device__ __forceinline__ void mma16816(float* d, const uint32_t* a, const uint32_t* b) {
    asm volatile(
        "mma.sync.aligned.m16n8k16.row.col.f32.f16.f16.f32 "
        "{%0,%1,%2,%3}, {%4,%5,%6,%7}, {%8,%9}, {%0,%1,%2,%3};"
        : "+f"(d[0]), "+f"(d[1]), "+f"(d[2]), "+f"(d[3])
        : "r"(a[0]), "r"(a[1]), "r"(a[2]), "r"(a[3]), "r"(b[0]), "r"(b[1]));
}
// pack two fp32 into fp16x2 (v0 -> low half, v1 -> high half)
__device__ __forceinline__ uint32_t pack_f16(float v0, float v1) {
    uint32_t r;
    asm("cvt.rn.f16x2.f32 %0, %1, %2;" : "=r"(r) : "f"(v1), "f"(v0));
    return r;
}
// residual after fp16 rounding, packed fp16x2
__device__ __forceinline__ uint32_t pack_f16_res(float v0, float v1) {
    float h0 = __half2float(__float2half_rn(v0));
    float h1 = __half2float(__float2half_rn(v1));
    return pack_f16(v0 - h0, v1 - h1);
}

// =============================================================================
// Prep: W -> fp16 image of 8192*W in exact mma B-fragment order.
// Entry e = ((c*4+ks)*8 + t)*32 + l
// =============================================================================
__global__ void prep_b_kernel(const float* __restrict__ W) {
    int e = blockIdx.x * blockDim.x + threadIdx.x;
    if (e >= BFRAG_N) return;
    int l  = e & 31;
    int t  = (e >> 5) & 7;
    int ks = (e >> 8) & 3;
    int c  = e >> 10;
    int r = l & 3, ncol = l >> 2;
    int n0 = t * 16 + ncol, n1 = n0 + 8;
    int kb = ks * 16 + 2 * r;
    const float* Wc = W + (size_t)c * CIN * COUT;
    float v0 = WSCALE * Wc[(size_t)(kb + 0) * COUT + n0];
    float v1 = WSCALE * Wc[(size_t)(kb + 1) * COUT + n0];
    float v2 = WSCALE * Wc[(size_t)(kb + 8) * COUT + n0];
    float v3 = WSCALE * Wc[(size_t)(kb + 9) * COUT + n0];
    float v4 = WSCALE * Wc[(size_t)(kb + 0) * COUT + n1];
    float v5 = WSCALE * Wc[(size_t)(kb + 1) * COUT + n1];
    float v6 = WSCALE * Wc[(size_t)(kb + 8) * COUT + n1];
    float v7 = WSCALE * Wc[(size_t)(kb + 9) * COUT + n1];
    uint4 bq;
    bq.x = pack_f16(v0, v1); bq.y = pack_f16(v2, v3);
    bq.z = pack_f16(v4, v5); bq.w = pack_f16(v6, v7);
    g_Bfrag[e] = bq;
}

// =============================================================================
// Fused kernel. 8 warps: wk = wid&1 (k32 half), wn = wid>>1 (n32 block 0..3).
// Warp tile m32 x n32 x k32; fp16x2 split (A = Ah+Al vs fp16 B).
// =============================================================================
__global__ __launch_bounds__(NTHR, 2)
void fused_mma_kernel(const float* __restrict__ features,
                      const float* __restrict__ center,
                      const int* __restrict__ voxel_idx,
                      const int* __restrict__ num_list,
                      const float* __restrict__ gamma,
                      const float* __restrict__ beta,
                      float* __restrict__ outF,
                      float* __restrict__ outC,
                      int N, int M, int B, int K, int BK)
{
    __shared__ __align__(16) unsigned char sA[A_BUF * 2];   // 18432; overlaid by merge buf
    __shared__ int    sIdx[TM * CHUNKS];
    __shared__ int    sSrc[TM];
    __shared__ int    sVal[TM];
    __shared__ float2 sRed[TM * 4];

    const uint32_t sAb = smem_u32(sA);
    const int tid = threadIdx.x;
    const int r0  = blockIdx.x * TM;

    // ---- bookkeeping + coords (tid < 32) ----
    if (tid < TM) {
        int g = r0 + tid;
        int valid = 0, srcRow = 0, b = 0;
        if (g < BK) {
            b = g / K;
            int j = g - b * K;
            int off = 0;
            for (int bb = 0; bb < b; bb++) off += num_list[bb];
            int nl = num_list[b];
            int end = nl < K ? nl : K;
            valid = (j < end) ? 1 : 0;
            long long s = (long long)off + j;
            if (s < 0) s = 0;
            if (s > (long long)(M - 1)) s = M - 1;
            srcRow = (int)s;
        }
        sVal[tid] = valid;
        sSrc[tid] = srcRow;
        if (g < BK) {
            float c0 = (b < B - 1) ? (float)(b + 1) : 0.0f;
            float x = 0.f, y = 0.f, z = 0.f;
            if (valid) {
                x = center[(size_t)srcRow * 3 + 0];
                y = center[(size_t)srcRow * 3 + 1];
                z = center[(size_t)srcRow * 3 + 2];
            }
            *(float4*)(outC + (size_t)g * 4) = make_float4(c0, x, y, z);
        }
    }
    __syncthreads();

    // ---- stage neighbor indices ----
    for (int e = tid; e < TM * CHUNKS; e += NTHR) {
        int m = e / CHUNKS, c = e - m * CHUNKS;
        int v = voxel_idx[(size_t)sSrc[m] * CHUNKS + c];
        sIdx[e] = (v < 0) ? -1 : (v > N - 1 ? N - 1 : v);
    }
    __syncthreads();

    // producer mapping: row m (0..31), 8 channels (q*8..q*8+7)
    const int m = tid >> 3, q = tid & 7;
    // consumer mapping
    const int l   = tid & 31;
    const int wid = tid >> 5;          // 0..7
    const int wk  = wid & 1;           // k32 half: ks in {2wk, 2wk+1}
    const int wn  = wid >> 1;          // n32 block 0..3
    const uint32_t aOffBase = (uint32_t)((l & 15) * A_ROW + ((l >> 4) << 4));

    float acc[2][2][2][4];   // [f m16][t n16][g n8][4 regs]
    #pragma unroll
    for (int f = 0; f < 2; f++)
        #pragma unroll
        for (int t = 0; t < 2; t++)
            #pragma unroll
            for (int g = 0; g < 2; g++)
                #pragma unroll
                for (int i = 0; i < 4; i++) acc[f][t][g][i] = 0.0f;

    auto gatherA = [&](int c, float4* fa) {
        int idx = sIdx[m * CHUNKS + c];
        if (idx >= 0) {
            const float4* p = (const float4*)features + (size_t)idx * 16 + q * 2;
            fa[0] = p[0];
            fa[1] = p[1];
        } else {
            fa[0] = make_float4(0.f, 0.f, 0.f, 0.f);
            fa[1] = make_float4(0.f, 0.f, 0.f, 0.f);
        }
    };
    // B for one phase (c, ks2): 2 n16 blocks = 2 uint4
    auto loadB = [&](int c, int ks2, uint4 (&Bq)[2]) {
        size_t base = ((size_t)(c * 4 + 2 * wk + ks2) * 8 + 2 * wn) * 32 + l;
        Bq[0] = g_Bfrag[base];
        Bq[1] = g_Bfrag[base + 32];
    };
    auto convertStoreA = [&](const float4* fa, int abuf) {
        uint32_t hi[4], lo[4];
        const float* ff = (const float*)fa;
        #pragma unroll
        for (int i = 0; i < 4; i++) {
            hi[i] = pack_f16(ff[2 * i], ff[2 * i + 1]);
            lo[i] = pack_f16_res(ff[2 * i], ff[2 * i + 1]);
        }
        uint32_t aB = sAb + abuf * A_BUF + m * A_ROW + q * 16;
        sts128(aB,          hi);
        sts128(aB + A_HALF, lo);
    };
    // one mma phase: ks = 2wk + ks2 on A buffer of chunk c (16 mmas)
    auto phase = [&](int c, int ks2, uint4 (&Bq)[2]) {
        const int ks = 2 * wk + ks2;
        const uint32_t aBase = sAb + (c & 1) * A_BUF + aOffBase + ks * 32;
        #pragma unroll
        for (int f = 0; f < 2; f++) {
            uint32_t ah[4], al[4];
            ldsm4(ah, aBase + f * 16 * A_ROW);
            ldsm4(al, aBase + A_HALF + f * 16 * A_ROW);
            #pragma unroll
            for (int t = 0; t < 2; t++) {
                const uint32_t* bq = (const uint32_t*)&Bq[t];
                #pragma unroll
                for (int g = 0; g < 2; g++) {
                    float* a = acc[f][t][g];
                    mma16816(a, ah, bq + g * 2);   // Ah * B
                    mma16816(a, al, bq + g * 2);   // Al * B
                }
            }
        }
    };

    uint4 P0[2], P1[2];
    float4 fa[2];

    // ---- prologue: B(0, ks2=0), A(0) staged, fa holds A(1) ----
    loadB(0, 0, P0);
    gatherA(0, fa);
    convertStoreA(fa, 0);
    gatherA(1, fa);
    __syncthreads();

    #pragma unroll 1
    for (int c = 0; c < CHUNKS; c++) {
        loadB(c, 1, P1);                         // B for phase (c,1)
        phase(c, 0, P0);
        if (c + 1 < CHUNKS) loadB(c + 1, 0, P0); // B for next chunk ph0
        phase(c, 1, P1);
        if (c + 1 < CHUNKS) {
            convertStoreA(fa, (c + 1) & 1);
            if (c + 2 < CHUNKS) gatherA(c + 2, fa);
        }
        __syncthreads();
    }

    // ---- merge K partials: wk=1 -> smem, wk=0 adds; descale by 1/8192 ----
    float* sM = (float*)sA;     // [4 su][32 lanes][stride 33] = 16896 B
    const int su = wid >> 1;    // 0..3 shared by the wk pair
    if (wk == 1) {
        float* dst = sM + ((size_t)su * 32 + l) * 33;
        #pragma unroll
        for (int f = 0; f < 2; f++)
            #pragma unroll
            for (int t = 0; t < 2; t++)
                #pragma unroll
                for (int g = 0; g < 2; g++)
                    #pragma unroll
                    for (int i = 0; i < 4; i++)
                        dst[((f * 2 + t) * 2 + g) * 4 + i] = acc[f][t][g][i];
    }
    __syncthreads();
    if (wk == 0) {
        const float* src = sM + ((size_t)su * 32 + l) * 33;
        #pragma unroll
        for (int f = 0; f < 2; f++)
            #pragma unroll
            for (int t = 0; t < 2; t++)
                #pragma unroll
                for (int g = 0; g < 2; g++)
                    #pragma unroll
                    for (int i = 0; i < 4; i++)
                        acc[f][t][g][i] =
                            (acc[f][t][g][i] + src[((f * 2 + t) * 2 + g) * 4 + i])
                            * INV_WSCALE;

        // LN partial stats: rows f*16 + h*8 + (l>>2), cols n32 of wn
        #pragma unroll
        for (int f = 0; f < 2; f++) {
            #pragma unroll
            for (int h = 0; h < 2; h++) {
                float s = 0.f, sq = 0.f;
                #pragma unroll
                for (int t = 0; t < 2; t++)
                    #pragma unroll
                    for (int g = 0; g < 2; g++) {
                        float v0 = acc[f][t][g][h * 2], v1 = acc[f][t][g][h * 2 + 1];
                        s += v0 + v1;
                        sq += v0 * v0 + v1 * v1;
                    }
                s  += __shfl_xor_sync(0xffffffffu, s, 1);
                sq += __shfl_xor_sync(0xffffffffu, sq, 1);
                s  += __shfl_xor_sync(0xffffffffu, s, 2);
                sq += __shfl_xor_sync(0xffffffffu, sq, 2);
                if ((l & 3) == 0) {
                    int R = f * 16 + h * 8 + (l >> 2);
                    sRed[R * 4 + wn] = make_float2(s, sq);
                }
            }
        }
    }
    __syncthreads();

    if (wk == 0) {
        const float invC = 1.0f / (float)COUT;
        #pragma unroll
        for (int f = 0; f < 2; f++) {
            #pragma unroll
            for (int h = 0; h < 2; h++) {
                int R = f * 16 + h * 8 + (l >> 2);
                float2 p0 = sRed[R * 4 + 0], p1 = sRed[R * 4 + 1];
                float2 p2 = sRed[R * 4 + 2], p3 = sRed[R * 4 + 3];
                float st  = p0.x + p1.x + p2.x + p3.x;
                float sqt = p0.y + p1.y + p2.y + p3.y;
                float mu  = st * invC;
                float var = sqt * invC - mu * mu;
                float rs  = rsqrtf(var + 1e-3f);
                int valid = sVal[R];
                int grow  = r0 + R;
                if (grow < BK) {
                    float* op = outF + (size_t)grow * COUT;
                    #pragma unroll
                    for (int t = 0; t < 2; t++) {
                        #pragma unroll
                        for (int g = 0; g < 2; g++) {
                            int C = wn * 32 + t * 16 + g * 8 + (l & 3) * 2;
                            float2 gm = *(const float2*)(gamma + C);
                            float2 bt = *(const float2*)(beta + C);
                            float v0 = acc[f][t][g][h * 2];
                            float v1 = acc[f][t][g][h * 2 + 1];
                            float2 o;
                            o.x = valid ? fmaxf((v0 - mu) * rs * gm.x + bt.x, 0.f) : 0.f;
                            o.y = valid ? fmaxf((v1 - mu) * rs * gm.y + bt.y, 0.f) : 0.f;
                            *(float2*)(op + C) = o;
                        }
                    }
                }
            }
        }
    }
}

// =============================================================================
extern "C" void kernel_launch(void* const* d_in, const int* in_sizes, int n_in,
                              void* d_out, int out_size)
{
    const float* features = (const float*)d_in[0];
    const float* center   = (const float*)d_in[1];
    const int*   voxel    = (const int*)d_in[2];     // int32 (JAX x64 disabled)
    const int*   num_list = (const int*)d_in[3];
    const float* W        = (const float*)d_in[4];
    const float* gamma    = (const float*)d_in[5];
    const float* beta     = (const float*)d_in[6];

    int B    = in_sizes[3];
    int Cout = in_sizes[5];
    int M    = in_sizes[1] / 3;
    int K3r  = in_sizes[2] / M;
    int Cin  = in_sizes[4] / (K3r * Cout);
    int N    = in_sizes[0] / Cin;
    int K    = out_size / (B * (Cout + 4));
    int BK   = B * K;

    float* out  = (float*)d_out;
    float* outC = out + (size_t)BK * Cout;

    prep_b_kernel<<<(BFRAG_N + 255) / 256, 256>>>(W);

    int grid = (BK + TM - 1) / TM;
    fused_mma_kernel<<<grid, NTHR>>>(
        features, center, voxel, num_list, gamma, beta, out, outC,
        N, M, B, K, BK);
}

// round 16
// speedup vs baseline: 2.1884x; 1.2440x over previous
#include <cuda_runtime.h>
#include <cuda_fp16.h>
#include <cstdint>

// ---------------- problem shape constants ----------------
#define CHUNKS 27      // K3 neighbors = 27 K-chunks of 64
#define CIN    64
#define COUT   128
#define TM     32      // rows per CTA (2 CTAs/SM)
#define NTHR   256     // 8 warps: 4N x 2K, warp tile m32 x n32 x k32

#define WSCALE    8192.0f
#define INV_WSCALE (1.0f / 8192.0f)

// A smem: 2 buffers x 32x144B (fp16 A only, no residual)
#define A_ROW   144
#define A_TILE  (32 * A_ROW)        // 4608
// merge overlay needs [4][32][33] floats = 16896 B > 2*A_TILE
#define SA_BYTES 16896

// B fragment image: [27][4 ks][8 n16blk][32 lanes] x uint4 (fp16 of 8192*W)
#define BFRAG_N (CHUNKS * 4 * 8 * 32)
__device__ __align__(16) uint4 g_Bfrag[BFRAG_N];

// ---------------- asm helpers ----------------
__device__ __forceinline__ uint32_t smem_u32(const void* p) {
    return (uint32_t)__cvta_generic_to_shared(p);
}
__device__ __forceinline__ void sts128(uint32_t addr, const uint32_t* r) {
    asm volatile("st.shared.v4.b32 [%0], {%1,%2,%3,%4};"
                 :: "r"(addr), "r"(r[0]), "r"(r[1]), "r"(r[2]), "r"(r[3]) : "memory");
}
__device__ __forceinline__ void ldsm4(uint32_t* r, uint32_t addr) {
    asm volatile("ldmatrix.sync.aligned.m8n8.x4.shared.b16 {%0,%1,%2,%3}, [%4];"
                 : "=r"(r[0]), "=r"(r[1]), "=r"(r[2]), "=r"(r[3]) : "r"(addr));
}
__device__ __forceinline__ void mma16816(float* d, const uint32_t* a, const uint32_t* b) {
    asm volatile(
        "mma.sync.aligned.m16n8k16.row.col.f32.f16.f16.f32 "
        "{%0,%1,%2,%3}, {%4,%5,%6,%7}, {%8,%9}, {%0,%1,%2,%3};"
        : "+f"(d[0]), "+f"(d[1]), "+f"(d[2]), "+f"(d[3])
        : "r"(a[0]), "r"(a[1]), "r"(a[2]), "r"(a[3]), "r"(b[0]), "r"(b[1]));
}
// pack two fp32 into fp16x2 (v0 -> low half, v1 -> high half)
__device__ __forceinline__ uint32_t pack_f16(float v0, float v1) {
    uint32_t r;
    asm("cvt.rn.f16x2.f32 %0, %1, %2;" : "=r"(r) : "f"(v1), "f"(v0));
    return r;
}

// =============================================================================
// Prep: W -> fp16 image of 8192*W in exact mma B-fragment order.
// Entry e = ((c*4+ks)*8 + t)*32 + l
// =============================================================================
__global__ void prep_b_kernel(const float* __restrict__ W) {
    int e = blockIdx.x * blockDim.x + threadIdx.x;
    if (e >= BFRAG_N) return;
    int l  = e & 31;
    int t  = (e >> 5) & 7;
    int ks = (e >> 8) & 3;
    int c  = e >> 10;
    int r = l & 3, ncol = l >> 2;
    int n0 = t * 16 + ncol, n1 = n0 + 8;
    int kb = ks * 16 + 2 * r;
    const float* Wc = W + (size_t)c * CIN * COUT;
    float v0 = WSCALE * Wc[(size_t)(kb + 0) * COUT + n0];
    float v1 = WSCALE * Wc[(size_t)(kb + 1) * COUT + n0];
    float v2 = WSCALE * Wc[(size_t)(kb + 8) * COUT + n0];
    float v3 = WSCALE * Wc[(size_t)(kb + 9) * COUT + n0];
    float v4 = WSCALE * Wc[(size_t)(kb + 0) * COUT + n1];
    float v5 = WSCALE * Wc[(size_t)(kb + 1) * COUT + n1];
    float v6 = WSCALE * Wc[(size_t)(kb + 8) * COUT + n1];
    float v7 = WSCALE * Wc[(size_t)(kb + 9) * COUT + n1];
    uint4 bq;
    bq.x = pack_f16(v0, v1); bq.y = pack_f16(v2, v3);
    bq.z = pack_f16(v4, v5); bq.w = pack_f16(v6, v7);
    g_Bfrag[e] = bq;
}

// =============================================================================
// Fused kernel. 8 warps: wk = wid&1 (k32 half), wn = wid>>1 (n32 block 0..3).
// Warp tile m32 x n32 x k32; single-pass fp16 A x fp16 B (8 mma/phase).
// =============================================================================
__global__ __launch_bounds__(NTHR, 2)
void fused_mma_kernel(const float* __restrict__ features,
                      const float* __restrict__ center,
                      const int* __restrict__ voxel_idx,
                      const int* __restrict__ num_list,
                      const float* __restrict__ gamma,
                      const float* __restrict__ beta,
                      float* __restrict__ outF,
                      float* __restrict__ outC,
                      int N, int M, int B, int K, int BK)
{
    __shared__ __align__(16) unsigned char sA[SA_BYTES];   // A tiles; overlaid by merge buf
    __shared__ int    sIdx[TM * CHUNKS];
    __shared__ int    sSrc[TM];
    __shared__ int    sVal[TM];
    __shared__ float2 sRed[TM * 4];

    const uint32_t sAb = smem_u32(sA);
    const int tid = threadIdx.x;
    const int r0  = blockIdx.x * TM;

    // ---- bookkeeping + coords (tid < 32) ----
    if (tid < TM) {
        int g = r0 + tid;
        int valid = 0, srcRow = 0, b = 0;
        if (g < BK) {
            b = g / K;
            int j = g - b * K;
            int off = 0;
            for (int bb = 0; bb < b; bb++) off += num_list[bb];
            int nl = num_list[b];
            int end = nl < K ? nl : K;
            valid = (j < end) ? 1 : 0;
            long long s = (long long)off + j;
            if (s < 0) s = 0;
            if (s > (long long)(M - 1)) s = M - 1;
            srcRow = (int)s;
        }
        sVal[tid] = valid;
        sSrc[tid] = srcRow;
        if (g < BK) {
            float c0 = (b < B - 1) ? (float)(b + 1) : 0.0f;
            float x = 0.f, y = 0.f, z = 0.f;
            if (valid) {
                x = center[(size_t)srcRow * 3 + 0];
                y = center[(size_t)srcRow * 3 + 1];
                z = center[(size_t)srcRow * 3 + 2];
            }
            *(float4*)(outC + (size_t)g * 4) = make_float4(c0, x, y, z);
        }
    }
    __syncthreads();

    // ---- stage neighbor indices ----
    for (int e = tid; e < TM * CHUNKS; e += NTHR) {
        int m = e / CHUNKS, c = e - m * CHUNKS;
        int v = voxel_idx[(size_t)sSrc[m] * CHUNKS + c];
        sIdx[e] = (v < 0) ? -1 : (v > N - 1 ? N - 1 : v);
    }
    __syncthreads();

    // producer mapping: row m (0..31), 8 channels (q*8..q*8+7)
    const int m = tid >> 3, q = tid & 7;
    // consumer mapping
    const int l   = tid & 31;
    const int wid = tid >> 5;          // 0..7
    const int wk  = wid & 1;           // k32 half: ks in {2wk, 2wk+1}
    const int wn  = wid >> 1;          // n32 block 0..3
    const uint32_t aOffBase = (uint32_t)((l & 15) * A_ROW + ((l >> 4) << 4));

    float acc[2][2][2][4];   // [f m16][t n16][g n8][4 regs]
    #pragma unroll
    for (int f = 0; f < 2; f++)
        #pragma unroll
        for (int t = 0; t < 2; t++)
            #pragma unroll
            for (int g = 0; g < 2; g++)
                #pragma unroll
                for (int i = 0; i < 4; i++) acc[f][t][g][i] = 0.0f;

    auto gatherA = [&](int c, float4* fa) {
        int idx = sIdx[m * CHUNKS + c];
        if (idx >= 0) {
            const float4* p = (const float4*)features + (size_t)idx * 16 + q * 2;
            fa[0] = p[0];
            fa[1] = p[1];
        } else {
            fa[0] = make_float4(0.f, 0.f, 0.f, 0.f);
            fa[1] = make_float4(0.f, 0.f, 0.f, 0.f);
        }
    };
    // B for one phase (c, ks2): 2 n16 blocks = 2 uint4
    auto loadB = [&](int c, int ks2, uint4 (&Bq)[2]) {
        size_t base = ((size_t)(c * 4 + 2 * wk + ks2) * 8 + 2 * wn) * 32 + l;
        Bq[0] = g_Bfrag[base];
        Bq[1] = g_Bfrag[base + 32];
    };
    auto convertStoreA = [&](const float4* fa, int abuf) {
        uint32_t hi[4];
        const float* ff = (const float*)fa;
        #pragma unroll
        for (int i = 0; i < 4; i++)
            hi[i] = pack_f16(ff[2 * i], ff[2 * i + 1]);
        sts128(sAb + abuf * A_TILE + m * A_ROW + q * 16, hi);
    };
    // one mma phase: ks = 2wk + ks2 on A buffer of chunk c (8 mmas)
    auto phase = [&](int c, int ks2, uint4 (&Bq)[2]) {
        const int ks = 2 * wk + ks2;
        const uint32_t aBase = sAb + (c & 1) * A_TILE + aOffBase + ks * 32;
        #pragma unroll
        for (int f = 0; f < 2; f++) {
            uint32_t ah[4];
            ldsm4(ah, aBase + f * 16 * A_ROW);
            #pragma unroll
            for (int t = 0; t < 2; t++) {
                const uint32_t* bq = (const uint32_t*)&Bq[t];
                #pragma unroll
                for (int g = 0; g < 2; g++)
                    mma16816(acc[f][t][g], ah, bq + g * 2);
            }
        }
    };

    uint4 P0[2], P1[2];
    float4 fa[2];

    // ---- prologue: B(0, ks2=0), A(0) staged, fa holds A(1) ----
    loadB(0, 0, P0);
    gatherA(0, fa);
    convertStoreA(fa, 0);
    gatherA(1, fa);
    __syncthreads();

    #pragma unroll 1
    for (int c = 0; c < CHUNKS; c++) {
        loadB(c, 1, P1);                         // B for phase (c,1)
        phase(c, 0, P0);
        if (c + 1 < CHUNKS) loadB(c + 1, 0, P0); // B for next chunk ph0
        phase(c, 1, P1);
        if (c + 1 < CHUNKS) {
            convertStoreA(fa, (c + 1) & 1);
            if (c + 2 < CHUNKS) gatherA(c + 2, fa);
        }
        __syncthreads();
    }

    // ---- merge K partials: wk=1 -> smem, wk=0 adds; descale by 1/8192 ----
    float* sM = (float*)sA;     // [4 su][32 lanes][stride 33] = 16896 B
    const int su = wid >> 1;    // 0..3 shared by the wk pair
    if (wk == 1) {
        float* dst = sM + ((size_t)su * 32 + l) * 33;
        #pragma unroll
        for (int f = 0; f < 2; f++)
            #pragma unroll
            for (int t = 0; t < 2; t++)
                #pragma unroll
                for (int g = 0; g < 2; g++)
                    #pragma unroll
                    for (int i = 0; i < 4; i++)
                        dst[((f * 2 + t) * 2 + g) * 4 + i] = acc[f][t][g][i];
    }
    __syncthreads();
    if (wk == 0) {
        const float* src = sM + ((size_t)su * 32 + l) * 33;
        #pragma unroll
        for (int f = 0; f < 2; f++)
            #pragma unroll
            for (int t = 0; t < 2; t++)
                #pragma unroll
                for (int g = 0; g < 2; g++)
                    #pragma unroll
                    for (int i = 0; i < 4; i++)
                        acc[f][t][g][i] =
                            (acc[f][t][g][i] + src[((f * 2 + t) * 2 + g) * 4 + i])
                            * INV_WSCALE;

        // LN partial stats: rows f*16 + h*8 + (l>>2), cols n32 of wn
        #pragma unroll
        for (int f = 0; f < 2; f++) {
            #pragma unroll
            for (int h = 0; h < 2; h++) {
                float s = 0.f, sq = 0.f;
                #pragma unroll
                for (int t = 0; t < 2; t++)
                    #pragma unroll
                    for (int g = 0; g < 2; g++) {
                        float v0 = acc[f][t][g][h * 2], v1 = acc[f][t][g][h * 2 + 1];
                        s += v0 + v1;
                        sq += v0 * v0 + v1 * v1;
                    }
                s  += __shfl_xor_sync(0xffffffffu, s, 1);
                sq += __shfl_xor_sync(0xffffffffu, sq, 1);
                s  += __shfl_xor_sync(0xffffffffu, s, 2);
                sq += __shfl_xor_sync(0xffffffffu, sq, 2);
                if ((l & 3) == 0) {
                    int R = f * 16 + h * 8 + (l >> 2);
                    sRed[R * 4 + wn] = make_float2(s, sq);
                }
            }
        }
    }
    __syncthreads();

    if (wk == 0) {
        const float invC = 1.0f / (float)COUT;
        #pragma unroll
        for (int f = 0; f < 2; f++) {
            #pragma unroll
            for (int h = 0; h < 2; h++) {
                int R = f * 16 + h * 8 + (l >> 2);
                float2 p0 = sRed[R * 4 + 0], p1 = sRed[R * 4 + 1];
                float2 p2 = sRed[R * 4 + 2], p3 = sRed[R * 4 + 3];
                float st  = p0.x + p1.x + p2.x + p3.x;
                float sqt = p0.y + p1.y + p2.y + p3.y;
                float mu  = st * invC;
                float var = sqt * invC - mu * mu;
                float rs  = rsqrtf(var + 1e-3f);
                int valid = sVal[R];
                int grow  = r0 + R;
                if (grow < BK) {
                    float* op = outF + (size_t)grow * COUT;
                    #pragma unroll
                    for (int t = 0; t < 2; t++) {
                        #pragma unroll
                        for (int g = 0; g < 2; g++) {
                            int C = wn * 32 + t * 16 + g * 8 + (l & 3) * 2;
                            float2 gm = *(const float2*)(gamma + C);
                            float2 bt = *(const float2*)(beta + C);
                            float v0 = acc[f][t][g][h * 2];
                            float v1 = acc[f][t][g][h * 2 + 1];
                            float2 o;
                            o.x = valid ? fmaxf((v0 - mu) * rs * gm.x + bt.x, 0.f) : 0.f;
                            o.y = valid ? fmaxf((v1 - mu) * rs * gm.y + bt.y, 0.f) : 0.f;
                            *(float2*)(op + C) = o;
                        }
                    }
                }
            }
        }
    }
}

// =============================================================================
extern "C" void kernel_launch(void* const* d_in, const int* in_sizes, int n_in,
                              void* d_out, int out_size)
{
    const float* features = (const float*)d_in[0];
    const float* center   = (const float*)d_in[1];
    const int*   voxel    = (const int*)d_in[2];     // int32 (JAX x64 disabled)
    const int*   num_list = (const int*)d_in[3];
    const float* W        = (const float*)d_in[4];
    const float* gamma    = (const float*)d_in[5];
    const float* beta     = (const float*)d_in[6];

    int B    = in_sizes[3];
    int Cout = in_sizes[5];
    int M    = in_sizes[1] / 3;
    int K3r  = in_sizes[2] / M;
    int Cin  = in_sizes[4] / (K3r * Cout);
    int N    = in_sizes[0] / Cin;
    int K    = out_size / (B * (Cout + 4));
    int BK   = B * K;

    float* out  = (float*)d_out;
    float* outC = out + (size_t)BK * Cout;

    prep_b_kernel<<<(BFRAG_N + 255) / 256, 256>>>(W);

    int grid = (BK + TM - 1) / TM;
    fused_mma_kernel<<<grid, NTHR>>>(
        features, center, voxel, num_list, gamma, beta, out, outC,
        N, M, B, K, BK);
}